// round 5
// baseline (speedup 1.0000x reference)
#include <cuda_runtime.h>
#include <cuda_fp16.h>
#include <cstdint>

#define NN 50000
#define EE 800000
#define CC 64
#define SAH 72
#define SBH 136
#define SCAN_BLK 512

// ---------------- device scratch ----------------
__device__ __align__(16) __half d_Wh[CC * 256];
__device__ __align__(16) float  d_Wr[CC * CC];
__device__ float  d_gauss[24];
__device__ __align__(16) __half d_Yh[NN * 256];
__device__ __align__(16) float  d_Yr[NN * CC];
__device__ __align__(16) float  d_h[NN * CC];
__device__ double d_stats[2 * CC];
__device__ __align__(16) float  d_bnA[CC];
__device__ __align__(16) float  d_bnB[CC];
// CSR build
__device__ int    d_rowcnt[NN];
__device__ int    d_rowstart[NN];
__device__ int    d_wptr[NN];
__device__ int    d_blksum[128];
__device__ int    d_blkoff[128];
__device__ int    d_csrc[EE];
__device__ int    d_cid[EE];
__device__ __align__(16) float4 d_w4[EE];

// ---------------- mma helpers ----------------
__device__ __forceinline__ void mma16816(float* c, const uint32_t* a, const uint32_t* b) {
    asm volatile(
        "mma.sync.aligned.m16n8k16.row.col.f32.f16.f16.f32 "
        "{%0,%1,%2,%3}, {%4,%5,%6,%7}, {%8,%9}, {%0,%1,%2,%3};"
        : "+f"(c[0]), "+f"(c[1]), "+f"(c[2]), "+f"(c[3])
        : "r"(a[0]), "r"(a[1]), "r"(a[2]), "r"(a[3]), "r"(b[0]), "r"(b[1]));
}
__device__ __forceinline__ void ldsm_x4(uint32_t* r, const __half* p) {
    uint32_t addr = (uint32_t)__cvta_generic_to_shared(p);
    asm volatile("ldmatrix.sync.aligned.m8n8.x4.shared.b16 {%0,%1,%2,%3}, [%4];"
                 : "=r"(r[0]), "=r"(r[1]), "=r"(r[2]), "=r"(r[3]) : "r"(addr));
}
__device__ __forceinline__ void ldsm_x4_trans(uint32_t* r, const __half* p) {
    uint32_t addr = (uint32_t)__cvta_generic_to_shared(p);
    asm volatile("ldmatrix.sync.aligned.m8n8.x4.trans.shared.b16 {%0,%1,%2,%3}, [%4];"
                 : "=r"(r[0]), "=r"(r[1]), "=r"(r[2]), "=r"(r[3]) : "r"(addr));
}

// ================= CSR build =================
__global__ void hist_zero_kernel(int n) {
    int i = threadIdx.x + blockIdx.x * blockDim.x;
    if (i < n) d_rowcnt[i] = 0;
}
__global__ void hist_kernel(const int* __restrict__ edges, int nE) {
    int e = threadIdx.x + blockIdx.x * blockDim.x;
    if (e < nE) atomicAdd(&d_rowcnt[edges[nE + e]], 1);
}
__global__ void scan_local_kernel(int n) {
    __shared__ int sm[SCAN_BLK];
    int t = threadIdx.x;
    int i = blockIdx.x * SCAN_BLK + t;
    int x = (i < n) ? d_rowcnt[i] : 0;
    int val = x;
    sm[t] = val;
    __syncthreads();
    for (int off = 1; off < SCAN_BLK; off <<= 1) {
        int v = (t >= off) ? sm[t - off] : 0;
        __syncthreads();
        val += v; sm[t] = val;
        __syncthreads();
    }
    if (i < n) d_rowstart[i] = val - x;      // exclusive
    if (t == SCAN_BLK - 1) d_blksum[blockIdx.x] = val;
}
__global__ void scan_blk_kernel(int nb) {
    __shared__ int sm[128];
    int t = threadIdx.x;
    int x = (t < nb) ? d_blksum[t] : 0;
    int val = x;
    sm[t] = val;
    __syncthreads();
    for (int off = 1; off < 128; off <<= 1) {
        int v = (t >= off) ? sm[t - off] : 0;
        __syncthreads();
        val += v; sm[t] = val;
        __syncthreads();
    }
    d_blkoff[t] = val - x;                   // exclusive
}
__global__ void scan_add_kernel(int n) {
    int i = threadIdx.x + blockIdx.x * blockDim.x;
    if (i < n) {
        int v = d_rowstart[i] + d_blkoff[i / SCAN_BLK];
        d_rowstart[i] = v;
        d_wptr[i] = v;
    }
}
__global__ void permute_kernel(const int* __restrict__ edges, int nE) {
    int e = threadIdx.x + blockIdx.x * blockDim.x;
    if (e >= nE) return;
    int dst = edges[nE + e];
    int pos = atomicAdd(&d_wptr[dst], 1);
    d_csrc[pos] = edges[e];
    d_cid[pos]  = e;
}

// ================= per-layer =================
__global__ void prep_kernel(const float* __restrict__ g, const float* __restrict__ root,
                            const float* __restrict__ dense, const float* __restrict__ mu,
                            const float* __restrict__ sigma) {
    int tid = threadIdx.x + blockIdx.x * blockDim.x;
    if (tid < CC * 256) d_Wh[tid] = __float2half_rn(g[tid]);
    if (tid < CC * CC)  d_Wr[tid] = root[tid] + dense[tid];
    if (tid < 12) {
        d_gauss[tid] = mu[tid];
        float s = sigma[tid];
        d_gauss[12 + tid] = 0.5f / (1e-15f + s * s);
    }
    if (tid < 2 * CC) d_stats[tid] = 0.0;
}

// per-edge gaussian weights, CSR order
__global__ void wk_kernel(const float* __restrict__ pseudo, int nE) {
    int i = threadIdx.x + blockIdx.x * blockDim.x;
    if (i >= nE) return;
    int e = __ldg(&d_cid[i]);
    float p0 = pseudo[e * 3 + 0];
    float p1 = pseudo[e * 3 + 1];
    float p2 = pseudo[e * 3 + 2];
    float w[4];
#pragma unroll
    for (int k = 0; k < 4; k++) {
        float q0 = p0 - d_gauss[k * 3 + 0];
        float q1 = p1 - d_gauss[k * 3 + 1];
        float q2 = p2 - d_gauss[k * 3 + 2];
        float t = q0 * q0 * d_gauss[12 + k * 3 + 0]
                + q1 * q1 * d_gauss[12 + k * 3 + 1]
                + q2 * q2 * d_gauss[12 + k * 3 + 2];
        w[k] = __expf(-t);
    }
    d_w4[i] = make_float4(w[0], w[1], w[2], w[3]);
}

// ---------- GEMM (g part, fp16 HMMA) ----------
__global__ __launch_bounds__(256) void gemm_g_kernel(const float* __restrict__ Xin,
                                                     int affine, int nrows) {
    const float* X = affine ? d_h : Xin;
    __shared__ __half sA[128 * SAH];
    __shared__ __half sB[64 * SBH];
    int tid  = threadIdx.x;
    int row0 = blockIdx.x * 128;
    int col0 = blockIdx.y * 128;
    {
        int r = tid >> 2, cg = tid & 3;
        const float4* src = reinterpret_cast<const float4*>(d_Wh + r * 256 + col0 + cg * 32);
        float4* dst = reinterpret_cast<float4*>(sB + r * SBH + cg * 32);
        dst[0] = src[0]; dst[1] = src[1]; dst[2] = src[2]; dst[3] = src[3];
    }
#pragma unroll
    for (int i = 0; i < 8; i++) {
        int t  = tid + i * 256;
        int r  = t >> 4;
        int c4 = (t & 15) << 2;
        float4 v = make_float4(0.f, 0.f, 0.f, 0.f);
        int gr = row0 + r;
        if (gr < nrows)
            v = *reinterpret_cast<const float4*>(X + (size_t)gr * CC + c4);
        if (affine) {
            float4 a = *reinterpret_cast<const float4*>(d_bnA + c4);
            float4 b = *reinterpret_cast<const float4*>(d_bnB + c4);
            v.x = fmaxf(v.x * a.x + b.x, 0.f);
            v.y = fmaxf(v.y * a.y + b.y, 0.f);
            v.z = fmaxf(v.z * a.z + b.z, 0.f);
            v.w = fmaxf(v.w * a.w + b.w, 0.f);
        }
        *reinterpret_cast<__half2*>(sA + r * SAH + c4)     = __floats2half2_rn(v.x, v.y);
        *reinterpret_cast<__half2*>(sA + r * SAH + c4 + 2) = __floats2half2_rn(v.z, v.w);
    }
    __syncthreads();

    int w    = tid >> 5;
    int lane = tid & 31;
    int wrow = w * 16;

    float acc[16][4];
#pragma unroll
    for (int n = 0; n < 16; n++)
#pragma unroll
        for (int j = 0; j < 4; j++) acc[n][j] = 0.f;

#pragma unroll
    for (int ks = 0; ks < 4; ks++) {
        uint32_t a[4];
        ldsm_x4(a, sA + (wrow + (lane & 15)) * SAH + ks * 16 + (lane >> 4) * 8);
        const __half* brow = sB + (ks * 16 + (lane & 15)) * SBH + (lane >> 4) * 8;
#pragma unroll
        for (int np = 0; np < 8; np++) {
            uint32_t b[4];
            ldsm_x4_trans(b, brow + np * 16);
            mma16816(acc[2 * np],     a, b);
            mma16816(acc[2 * np + 1], a, b + 2);
        }
    }

    int rA = row0 + wrow + (lane >> 2);
    int cB = col0 + ((lane & 3) << 1);
#pragma unroll
    for (int n = 0; n < 16; n++) {
        if (rA < nrows)
            *reinterpret_cast<__half2*>(d_Yh + (size_t)rA * 256 + cB + n * 8) =
                __floats2half2_rn(acc[n][0], acc[n][1]);
        if (rA + 8 < nrows)
            *reinterpret_cast<__half2*>(d_Yh + (size_t)(rA + 8) * 256 + cB + n * 8) =
                __floats2half2_rn(acc[n][2], acc[n][3]);
    }
}

// ---------- GEMM (root+dense, fp32) ----------
__global__ __launch_bounds__(256) void gemm_r_kernel(const float* __restrict__ Xin,
                                                     int affine, int nrows) {
    const float* X = affine ? d_h : Xin;
    __shared__ float sA[64 * 64];
    __shared__ float sB[64 * 64];
    int tid  = threadIdx.x;
    int row0 = blockIdx.x * 64;

#pragma unroll
    for (int i = 0; i < 4; i++) {
        int t  = tid + i * 256;
        int r  = t >> 4;
        int c4 = (t & 15) << 2;
        float4 v = make_float4(0.f, 0.f, 0.f, 0.f);
        if (row0 + r < nrows)
            v = *reinterpret_cast<const float4*>(X + (size_t)(row0 + r) * CC + c4);
        if (affine) {
            float4 a = *reinterpret_cast<const float4*>(d_bnA + c4);
            float4 b = *reinterpret_cast<const float4*>(d_bnB + c4);
            v.x = fmaxf(v.x * a.x + b.x, 0.f);
            v.y = fmaxf(v.y * a.y + b.y, 0.f);
            v.z = fmaxf(v.z * a.z + b.z, 0.f);
            v.w = fmaxf(v.w * a.w + b.w, 0.f);
        }
        *reinterpret_cast<float4*>(sA + r * 64 + c4) = v;
        *reinterpret_cast<float4*>(sB + r * 64 + c4) =
            *reinterpret_cast<const float4*>(d_Wr + r * 64 + c4);
    }
    __syncthreads();

    int tx = tid & 15, ty = tid >> 4;
    float acc[4][4];
#pragma unroll
    for (int i = 0; i < 4; i++)
#pragma unroll
        for (int j = 0; j < 4; j++) acc[i][j] = 0.f;

#pragma unroll 8
    for (int k = 0; k < 64; k++) {
        float4 b = *reinterpret_cast<float4*>(sB + k * 64 + (tx << 2));
        float a0 = sA[(ty * 4 + 0) * 64 + k];
        float a1 = sA[(ty * 4 + 1) * 64 + k];
        float a2 = sA[(ty * 4 + 2) * 64 + k];
        float a3 = sA[(ty * 4 + 3) * 64 + k];
        acc[0][0] += a0 * b.x; acc[0][1] += a0 * b.y; acc[0][2] += a0 * b.z; acc[0][3] += a0 * b.w;
        acc[1][0] += a1 * b.x; acc[1][1] += a1 * b.y; acc[1][2] += a1 * b.z; acc[1][3] += a1 * b.w;
        acc[2][0] += a2 * b.x; acc[2][1] += a2 * b.y; acc[2][2] += a2 * b.z; acc[2][3] += a2 * b.w;
        acc[3][0] += a3 * b.x; acc[3][1] += a3 * b.y; acc[3][2] += a3 * b.z; acc[3][3] += a3 * b.w;
    }

#pragma unroll
    for (int i = 0; i < 4; i++) {
        int r = row0 + ty * 4 + i;
        if (r < nrows)
            *reinterpret_cast<float4*>(d_Yr + (size_t)r * CC + (tx << 2)) =
                make_float4(acc[i][0], acc[i][1], acc[i][2], acc[i][3]);
    }
}

// ---------- CSR edge kernel: gather + aggregate + finalize + BN stats ----------
__device__ __forceinline__ void acc_edge(float& a0, float& a1,
                                         const __half2* r, const float4& w) {
    __half2 v0 = __ldg(r), v1 = __ldg(r + 32), v2 = __ldg(r + 64), v3 = __ldg(r + 96);
    float2 f;
    f = __half22float2(v0); a0 += w.x * f.x; a1 += w.x * f.y;
    f = __half22float2(v1); a0 += w.y * f.x; a1 += w.y * f.y;
    f = __half22float2(v2); a0 += w.z * f.x; a1 += w.z * f.y;
    f = __half22float2(v3); a0 += w.w * f.x; a1 += w.w * f.y;
}

__global__ __launch_bounds__(512) void edge_csr_kernel(const float* __restrict__ bias,
                                                       float* out, int to_out, int n) {
    __shared__ float sS[16][64];
    __shared__ float sS2[16][64];
    int w    = threadIdx.x >> 5;
    int lane = threadIdx.x & 31;
    int dst  = blockIdx.x * 16 + w;
    bool act = (dst < n);

    float h0 = 0.f, h1 = 0.f;
    if (act) {
        int start = __ldg(&d_rowstart[dst]);
        int deg   = __ldg(&d_rowcnt[dst]);
        const __half2* Y = reinterpret_cast<const __half2*>(d_Yh);
        float a0 = 0.f, a1 = 0.f;
        int j = 0;
        for (; j + 2 <= deg; j += 2) {
            int i0 = start + j;
            int sA = __ldg(&d_csrc[i0]);
            int sB = __ldg(&d_csrc[i0 + 1]);
            float4 wA = __ldg(&d_w4[i0]);
            float4 wB = __ldg(&d_w4[i0 + 1]);
            acc_edge(a0, a1, Y + (size_t)sA * 128 + lane, wA);
            acc_edge(a0, a1, Y + (size_t)sB * 128 + lane, wB);
        }
        if (j < deg) {
            int i0 = start + j;
            acc_edge(a0, a1, Y + (size_t)__ldg(&d_csrc[i0]) * 128 + lane, __ldg(&d_w4[i0]));
        }
        float inv = __fdividef(1.f, fmaxf((float)deg, 1.f));
        float2 yr = *reinterpret_cast<const float2*>(d_Yr + (size_t)dst * CC + 2 * lane);
        float2 bv = *reinterpret_cast<const float2*>(bias + 2 * lane);
        h0 = a0 * inv + yr.x + bv.x;
        h1 = a1 * inv + yr.y + bv.y;
        float* H = to_out ? out : d_h;
        *reinterpret_cast<float2*>(H + (size_t)dst * CC + 2 * lane) = make_float2(h0, h1);
    }
    sS [w][2 * lane]     = h0;
    sS [w][2 * lane + 1] = h1;
    sS2[w][2 * lane]     = h0 * h0;
    sS2[w][2 * lane + 1] = h1 * h1;
    __syncthreads();
    int t = threadIdx.x;
    if (t < 64) {
        float s = 0.f;
#pragma unroll
        for (int k = 0; k < 16; k++) s += sS[k][t];
        atomicAdd(&d_stats[t], (double)s);
    } else if (t < 128) {
        int c = t - 64;
        float s = 0.f;
#pragma unroll
        for (int k = 0; k < 16; k++) s += sS2[k][c];
        atomicAdd(&d_stats[CC + c], (double)s);
    }
}

// ---------- BN prep / apply ----------
__global__ void bnprep_kernel(const float* __restrict__ gamma, const float* __restrict__ beta, int n) {
    int c = threadIdx.x;
    double mean = d_stats[c] / (double)n;
    double var  = d_stats[CC + c] / (double)n - mean * mean;
    double inv  = rsqrt(var + 1e-5);
    d_bnA[c] = (float)((double)gamma[c] * inv);
    d_bnB[c] = (float)((double)beta[c] - mean * (double)gamma[c] * inv);
}
__global__ void bnapply_kernel(float* H, int n) {
    int i = threadIdx.x + blockIdx.x * blockDim.x;
    if (i >= n * (CC / 4)) return;
    float4 v = reinterpret_cast<float4*>(H)[i];
    int c4 = (i & 15) << 2;
    float4 a = *reinterpret_cast<float4*>(d_bnA + c4);
    float4 b = *reinterpret_cast<float4*>(d_bnB + c4);
    v.x = v.x * a.x + b.x;
    v.y = v.y * a.y + b.y;
    v.z = v.z * a.z + b.z;
    v.w = v.w * a.w + b.w;
    reinterpret_cast<float4*>(H)[i] = v;
}

// ---------------- host orchestration ----------------
static void run_layer(const float* x, int affine,
                      const float* g, const float* mu, const float* sigma,
                      const float* root, const float* bias, const float* dense,
                      const float* gamma, const float* beta,
                      float* out, int to_out, int N, int E, const float* pseudo) {
    prep_kernel<<<64, 256>>>(g, root, dense, mu, sigma);
    gemm_g_kernel<<<dim3((N + 127) / 128, 2), 256>>>(x, affine, N);
    gemm_r_kernel<<<(N + 63) / 64, 256>>>(x, affine, N);
    wk_kernel<<<(E + 255) / 256, 256>>>(pseudo, E);
    edge_csr_kernel<<<(N + 15) / 16, 512>>>(bias, out, to_out, N);
    bnprep_kernel<<<1, 64>>>(gamma, beta, N);
}

extern "C" void kernel_launch(void* const* d_in, const int* in_sizes, int n_in,
                              void* d_out, int out_size) {
    const float* vals   = (const float*)d_in[0];
    const int*   edges  = (const int*)  d_in[1];
    const float* pseudo = (const float*)d_in[2];

    const float* g0     = (const float*)d_in[3];
    const float* mu0    = (const float*)d_in[4];
    const float* sigma0 = (const float*)d_in[5];
    const float* root0  = (const float*)d_in[6];
    const float* bias0  = (const float*)d_in[7];
    const float* dense0 = (const float*)d_in[8];
    const float* gamma0 = (const float*)d_in[9];
    const float* beta0  = (const float*)d_in[10];

    const float* g1     = (const float*)d_in[11];
    const float* mu1    = (const float*)d_in[12];
    const float* sigma1 = (const float*)d_in[13];
    const float* root1  = (const float*)d_in[14];
    const float* bias1  = (const float*)d_in[15];
    const float* dense1 = (const float*)d_in[16];
    const float* gamma1 = (const float*)d_in[17];
    const float* beta1  = (const float*)d_in[18];

    float* out = (float*)d_out;

    int N = in_sizes[0] / CC;
    int E = in_sizes[1] / 2;
    int nb = (N + SCAN_BLK - 1) / SCAN_BLK;

    // ---- build CSR once (edges shared by both layers) ----
    hist_zero_kernel<<<(N + 255) / 256, 256>>>(N);
    hist_kernel<<<(E + 255) / 256, 256>>>(edges, E);
    scan_local_kernel<<<nb, SCAN_BLK>>>(N);
    scan_blk_kernel<<<1, 128>>>(nb);
    scan_add_kernel<<<(N + 255) / 256, 256>>>(N);
    permute_kernel<<<(E + 255) / 256, 256>>>(edges, E);

    // layer 0: vals -> d_h raw; BN+ReLU folded into layer-1 GEMM loads
    run_layer(vals, 0, g0, mu0, sigma0, root0, bias0, dense0, gamma0, beta0,
              out, /*to_out=*/0, N, E, pseudo);
    // layer 1: d_h -> out raw, then final BN
    run_layer(nullptr, 1, g1, mu1, sigma1, root1, bias1, dense1, gamma1, beta1,
              out, /*to_out=*/1, N, E, pseudo);
    bnapply_kernel<<<(N * 16 + 255) / 256, 256>>>(out, N);
}